// round 10
// baseline (speedup 1.0000x reference)
#include <cuda_runtime.h>
#include <cstdint>
#include <cstddef>

// ----------------------------------------------------------------------------
// LoRALinear: out = x @ Weff^T + b, Weff = W + 2*(gB@gA + lB@lA)
// Shapes: x[M=16384, K=1024], W[N=4096, K], b[N], adapters rank R=8.
// Strategy:
//   k1: tf32-round x into g_Xc
//   k2: fold LoRA into Weff, tf32-round, into g_Weff
//   k3: tiled tf32 mma.sync GEMM (BM=128, BN=256, BK=32), cp.async dbl-buffer
// ----------------------------------------------------------------------------

#define LORA_SCALE 2.0f

#define MAXM 16384
#define MAXK 1024
#define MAXN 4096

// scratch (device globals — allocation-free per harness rules)
__device__ float g_Xc[MAXM * MAXK];     // 64 MB
__device__ float g_Weff[MAXN * MAXK];   // 16 MB

__device__ __forceinline__ float f2tf32(float x) {
    uint32_t u;
    asm("cvt.rna.tf32.f32 %0, %1;" : "=r"(u) : "f"(x));
    return __uint_as_float(u);
}

// ---- kernel 1: round x to tf32 (RNA) ---------------------------------------
__global__ void cvt_x_kernel(const float4* __restrict__ x, int n4) {
    int i = blockIdx.x * blockDim.x + threadIdx.x;
    if (i >= n4) return;
    float4 v = x[i];
    float4 o;
    o.x = f2tf32(v.x);
    o.y = f2tf32(v.y);
    o.z = f2tf32(v.z);
    o.w = f2tf32(v.w);
    reinterpret_cast<float4*>(g_Xc)[i] = o;
}

// ---- kernel 2: Weff = tf32( W + SCALE*(gB@gA + lB@lA) ) --------------------
__global__ void weff_kernel(const float4* __restrict__ W,
                            const float4* __restrict__ gA,
                            const float*  __restrict__ gB,
                            const float4* __restrict__ lA,
                            const float*  __restrict__ lB,
                            int K4, int R, int total4) {
    int i = blockIdx.x * blockDim.x + threadIdx.x;
    if (i >= total4) return;
    int o  = i / K4;
    int d4 = i - o * K4;
    float4 acc = W[i];
    for (int r = 0; r < R; r++) {
        float gb = gB[o * R + r] * LORA_SCALE;
        float lb = lB[o * R + r] * LORA_SCALE;
        float4 ga = gA[r * K4 + d4];
        float4 la = lA[r * K4 + d4];
        acc.x += gb * ga.x + lb * la.x;
        acc.y += gb * ga.y + lb * la.y;
        acc.z += gb * ga.z + lb * la.z;
        acc.w += gb * ga.w + lb * la.w;
    }
    float4 out;
    out.x = f2tf32(acc.x);
    out.y = f2tf32(acc.y);
    out.z = f2tf32(acc.z);
    out.w = f2tf32(acc.w);
    reinterpret_cast<float4*>(g_Weff)[i] = out;
}

// ---- kernel 3: GEMM --------------------------------------------------------
#define BM 128
#define BN 256
#define BK 32
#define SST 36                     // smem row stride (floats): conflict-free
#define A_ELE (BM * SST)           // 4608 floats / stage
#define B_ELE (BN * SST)           // 9216 floats / stage
#define GEMM_SMEM_BYTES ((2 * A_ELE + 2 * B_ELE) * 4)   // 110592 B

__device__ __forceinline__ void cp16(uint32_t dst, const void* src) {
    asm volatile("cp.async.cg.shared.global [%0], [%1], 16;" :: "r"(dst), "l"(src));
}

__device__ __forceinline__ void mma8(float* c, const uint32_t* a, const uint32_t* b) {
    asm volatile(
        "mma.sync.aligned.m16n8k8.row.col.f32.tf32.tf32.f32 "
        "{%0,%1,%2,%3}, {%4,%5,%6,%7}, {%8,%9}, {%0,%1,%2,%3};"
        : "+f"(c[0]), "+f"(c[1]), "+f"(c[2]), "+f"(c[3])
        : "r"(a[0]), "r"(a[1]), "r"(a[2]), "r"(a[3]), "r"(b[0]), "r"(b[1]));
}

__device__ __forceinline__ void issue_tile(const float* Ag, const float* Bg, int K,
                                           uint32_t a_base, uint32_t b_base,
                                           int tid, int kt, int s) {
    int r0 = tid >> 3;           // 0..31
    int kq = tid & 7;            // 0..7 (float4 slot along K)
    int kof = kt * BK + kq * 4;
    #pragma unroll
    for (int i = 0; i < 4; i++) {   // A: 128 rows
        int row = r0 + 32 * i;
        uint32_t dst = a_base + (uint32_t)(s * A_ELE + row * SST + kq * 4) * 4u;
        cp16(dst, Ag + (size_t)row * K + kof);
    }
    #pragma unroll
    for (int i = 0; i < 8; i++) {   // B: 256 rows
        int row = r0 + 32 * i;
        uint32_t dst = b_base + (uint32_t)(s * B_ELE + row * SST + kq * 4) * 4u;
        cp16(dst, Bg + (size_t)row * K + kof);
    }
    asm volatile("cp.async.commit_group;" ::: "memory");
}

__global__ void __launch_bounds__(256, 1)
gemm_tf32_kernel(const float* __restrict__ bias, float* __restrict__ C,
                 int M, int N, int K) {
    extern __shared__ float smem[];
    uint32_t s_base = (uint32_t)__cvta_generic_to_shared(smem);
    uint32_t a_base = s_base;
    uint32_t b_base = s_base + (uint32_t)(2 * A_ELE) * 4u;

    const int tid  = threadIdx.x;
    const int lane = tid & 31;
    const int warp = tid >> 5;
    const int wm   = warp & 1;        // 2 warps over M (64 each)
    const int wn   = warp >> 1;       // 4 warps over N (64 each)
    const int bm   = blockIdx.y * BM;
    const int bn   = blockIdx.x * BN;

    const float* Ag = g_Xc   + (size_t)bm * K;
    const float* Bg = g_Weff + (size_t)bn * K;

    float c[4][8][4];
    #pragma unroll
    for (int mt = 0; mt < 4; mt++)
        #pragma unroll
        for (int nt = 0; nt < 8; nt++)
            #pragma unroll
            for (int r = 0; r < 4; r++)
                c[mt][nt][r] = 0.0f;

    const int KT = K / BK;   // 32
    issue_tile(Ag, Bg, K, a_base, b_base, tid, 0, 0);

    for (int kt = 0; kt < KT; kt++) {
        if (kt + 1 < KT) {
            issue_tile(Ag, Bg, K, a_base, b_base, tid, kt + 1, (kt + 1) & 1);
            asm volatile("cp.async.wait_group 1;" ::: "memory");
        } else {
            asm volatile("cp.async.wait_group 0;" ::: "memory");
        }
        __syncthreads();

        const uint32_t* Af = reinterpret_cast<const uint32_t*>(smem) + (kt & 1) * A_ELE;
        const uint32_t* Bf = reinterpret_cast<const uint32_t*>(smem) + 2 * A_ELE + (kt & 1) * B_ELE;

        #pragma unroll
        for (int kk = 0; kk < 4; kk++) {            // 4 x (k=8) steps
            const int k0 = kk * 8 + (lane & 3);
            uint32_t afr[4][4];
            uint32_t bfr[8][2];
            const int ar = wm * 64 + (lane >> 2);
            #pragma unroll
            for (int mt = 0; mt < 4; mt++) {
                const uint32_t* p = Af + (ar + mt * 16) * SST + k0;
                afr[mt][0] = p[0];
                afr[mt][1] = p[8 * SST];
                afr[mt][2] = p[4];
                afr[mt][3] = p[8 * SST + 4];
            }
            const int br = wn * 64 + (lane >> 2);
            #pragma unroll
            for (int nt = 0; nt < 8; nt++) {
                const uint32_t* p = Bf + (br + nt * 8) * SST + k0;
                bfr[nt][0] = p[0];
                bfr[nt][1] = p[4];
            }
            #pragma unroll
            for (int mt = 0; mt < 4; mt++)
                #pragma unroll
                for (int nt = 0; nt < 8; nt++)
                    mma8(c[mt][nt], afr[mt], bfr[nt]);
        }
        __syncthreads();
    }

    // epilogue: += bias, store float2
    #pragma unroll
    for (int mt = 0; mt < 4; mt++) {
        int row0 = bm + wm * 64 + mt * 16 + (lane >> 2);
        #pragma unroll
        for (int nt = 0; nt < 8; nt++) {
            int col = bn + wn * 64 + nt * 8 + (lane & 3) * 2;
            float2 bv = *reinterpret_cast<const float2*>(bias + col);
            float2 v0 = { c[mt][nt][0] + bv.x, c[mt][nt][1] + bv.y };
            float2 v1 = { c[mt][nt][2] + bv.x, c[mt][nt][3] + bv.y };
            *reinterpret_cast<float2*>(C + (size_t)row0 * N + col)       = v0;
            *reinterpret_cast<float2*>(C + (size_t)(row0 + 8) * N + col) = v1;
        }
    }
}

// ---- launch ----------------------------------------------------------------
extern "C" void kernel_launch(void* const* d_in, const int* in_sizes, int n_in,
                              void* d_out, int out_size) {
    (void)n_in; (void)out_size;
    const float* x  = (const float*)d_in[0];
    const float* W  = (const float*)d_in[1];
    const float* b  = (const float*)d_in[2];
    const float* gA = (const float*)d_in[3];
    const float* gB = (const float*)d_in[4];
    const float* lA = (const float*)d_in[5];
    const float* lB = (const float*)d_in[6];

    const int N = in_sizes[2];               // 4096
    const int K = in_sizes[1] / N;           // 1024
    const int R = in_sizes[4] / N;           // 8
    const int M = in_sizes[0] / K;           // 16384

    // k1: x -> tf32
    int n4 = (M * K) / 4;
    cvt_x_kernel<<<(n4 + 255) / 256, 256>>>((const float4*)x, n4);

    // k2: Weff
    int K4 = K / 4;
    int t4 = N * K4;
    weff_kernel<<<(t4 + 255) / 256, 256>>>((const float4*)W, (const float4*)gA, gB,
                                           (const float4*)lA, lB, K4, R, t4);

    // k3: GEMM
    cudaFuncSetAttribute(gemm_tf32_kernel,
                         cudaFuncAttributeMaxDynamicSharedMemorySize, GEMM_SMEM_BYTES);
    dim3 grid(N / BN, M / BM);   // (16, 128)
    gemm_tf32_kernel<<<grid, 256, GEMM_SMEM_BYTES>>>(b, (float*)d_out, M, N, K);
}

// round 12
// speedup vs baseline: 1.0706x; 1.0706x over previous
#include <cuda_runtime.h>
#include <cstdint>
#include <cstddef>

// ----------------------------------------------------------------------------
// LoRALinear: out = x @ Weff^T + b, Weff = W + 2*(gB@gA + lB@lA)
//   k1: tf32-round x -> g_Xc   (k-pair interleaved: [k0,k4,k1,k5,k2,k6,k3,k7])
//   k2: fold LoRA -> g_Weff    (same interleave)
//   k3: mma.sync tf32 GEMM, BM=128 BN=256 BK=32, 3-stage cp.async,
//       LDS.64 fragment loads (interleave makes (k,k+4) pairs contiguous)
// ----------------------------------------------------------------------------

#define LORA_SCALE 2.0f
#define MAXM 16384
#define MAXK 1024
#define MAXN 4096

__device__ float g_Xc[MAXM * MAXK];     // 64 MB scratch (permuted-k tf32)
__device__ float g_Weff[MAXN * MAXK];   // 16 MB scratch (permuted-k tf32)

__device__ __forceinline__ float f2tf32(float x) {
    uint32_t u;
    asm("cvt.rna.tf32.f32 %0, %1;" : "=r"(u) : "f"(x));
    return __uint_as_float(u);
}

// ---- kernel 1: round x to tf32 + k-pair interleave -------------------------
// each thread handles one 8-k group: out = [a.x,b.x,a.y,b.y,a.z,b.z,a.w,b.w]
__global__ void cvt_x_kernel(const float4* __restrict__ x, int n8) {
    int i = blockIdx.x * blockDim.x + threadIdx.x;
    if (i >= n8) return;
    float4 a = x[2 * i];
    float4 b = x[2 * i + 1];
    float4 o0, o1;
    o0.x = f2tf32(a.x); o0.y = f2tf32(b.x); o0.z = f2tf32(a.y); o0.w = f2tf32(b.y);
    o1.x = f2tf32(a.z); o1.y = f2tf32(b.z); o1.z = f2tf32(a.w); o1.w = f2tf32(b.w);
    float4* out = reinterpret_cast<float4*>(g_Xc);
    out[2 * i]     = o0;
    out[2 * i + 1] = o1;
}

// ---- kernel 2: Weff = tf32( W + SCALE*(gB@gA + lB@lA) ), interleaved -------
__global__ void weff_kernel(const float4* __restrict__ W,
                            const float4* __restrict__ gA,
                            const float*  __restrict__ gB,
                            const float4* __restrict__ lA,
                            const float*  __restrict__ lB,
                            int K8, int R, int total8) {
    int i = blockIdx.x * blockDim.x + threadIdx.x;
    if (i >= total8) return;
    int o  = i / K8;
    int g  = i - o * K8;            // 8-k group within row
    float4 acc0 = W[2 * i];
    float4 acc1 = W[2 * i + 1];
    int K4 = K8 * 2;
    for (int r = 0; r < R; r++) {
        float gb = gB[o * R + r] * LORA_SCALE;
        float lb = lB[o * R + r] * LORA_SCALE;
        float4 ga0 = gA[r * K4 + 2 * g],     ga1 = gA[r * K4 + 2 * g + 1];
        float4 la0 = lA[r * K4 + 2 * g],     la1 = lA[r * K4 + 2 * g + 1];
        acc0.x += gb * ga0.x + lb * la0.x;
        acc0.y += gb * ga0.y + lb * la0.y;
        acc0.z += gb * ga0.z + lb * la0.z;
        acc0.w += gb * ga0.w + lb * la0.w;
        acc1.x += gb * ga1.x + lb * la1.x;
        acc1.y += gb * ga1.y + lb * la1.y;
        acc1.z += gb * ga1.z + lb * la1.z;
        acc1.w += gb * ga1.w + lb * la1.w;
    }
    float4 o0, o1;
    o0.x = f2tf32(acc0.x); o0.y = f2tf32(acc1.x);
    o0.z = f2tf32(acc0.y); o0.w = f2tf32(acc1.y);
    o1.x = f2tf32(acc0.z); o1.y = f2tf32(acc1.z);
    o1.z = f2tf32(acc0.w); o1.w = f2tf32(acc1.w);
    float4* out = reinterpret_cast<float4*>(g_Weff);
    out[2 * i]     = o0;
    out[2 * i + 1] = o1;
}

// ---- kernel 3: GEMM --------------------------------------------------------
#define BM 128
#define BN 256
#define BK 32
#define NS 3                        // pipeline stages
#define SST 40                      // smem row stride (floats): conflict-free
#define A_ELE (BM * SST)            // 5120 floats / stage
#define B_ELE (BN * SST)            // 10240 floats / stage
#define STAGE_ELE (A_ELE + B_ELE)   // 15360 floats
#define GEMM_SMEM_BYTES (NS * STAGE_ELE * 4)   // 184320 B

__device__ __forceinline__ void cp16(uint32_t dst, const void* src) {
    asm volatile("cp.async.cg.shared.global [%0], [%1], 16;" :: "r"(dst), "l"(src));
}

__device__ __forceinline__ void mma8(float* c, const uint32_t* a, const uint32_t* b) {
    asm volatile(
        "mma.sync.aligned.m16n8k8.row.col.f32.tf32.tf32.f32 "
        "{%0,%1,%2,%3}, {%4,%5,%6,%7}, {%8,%9}, {%0,%1,%2,%3};"
        : "+f"(c[0]), "+f"(c[1]), "+f"(c[2]), "+f"(c[3])
        : "r"(a[0]), "r"(a[1]), "r"(a[2]), "r"(a[3]), "r"(b[0]), "r"(b[1]));
}

// issue cp.async group for K-tile kt into slot s (always commits a group)
__device__ __forceinline__ void issue_tile(const float* Ag, const float* Bg, int K,
                                           int KT, uint32_t a_base, uint32_t b_base,
                                           int tid, int kt, int s) {
    if (kt < KT) {
        int r0  = tid >> 3;            // 0..31
        int kq  = tid & 7;             // 16B chunk along (permuted) K
        int kof = kt * BK + kq * 4;    // permuted scratch is linear per 16B chunk
        #pragma unroll
        for (int i = 0; i < 4; i++) {  // A: 128 rows
            int row = r0 + 32 * i;
            uint32_t dst = a_base + (uint32_t)(s * STAGE_ELE + row * SST + kq * 4) * 4u;
            cp16(dst, Ag + (size_t)row * K + kof);
        }
        #pragma unroll
        for (int i = 0; i < 8; i++) {  // B: 256 rows
            int row = r0 + 32 * i;
            uint32_t dst = b_base + (uint32_t)(s * STAGE_ELE + row * SST + kq * 4) * 4u;
            cp16(dst, Bg + (size_t)row * K + kof);
        }
    }
    asm volatile("cp.async.commit_group;" ::: "memory");
}

__global__ void __launch_bounds__(256, 1)
gemm_tf32_kernel(const float* __restrict__ bias, float* __restrict__ C,
                 int M, int N, int K) {
    extern __shared__ float smem[];
    uint32_t s_base = (uint32_t)__cvta_generic_to_shared(smem);
    uint32_t a_base = s_base;
    uint32_t b_base = s_base + (uint32_t)A_ELE * 4u;

    const int tid  = threadIdx.x;
    const int lane = tid & 31;
    const int warp = tid >> 5;
    const int wm   = warp & 1;        // 2 warps over M (64 each)
    const int wn   = warp >> 1;       // 4 warps over N (64 each)
    const int bm   = blockIdx.y * BM;
    const int bn   = blockIdx.x * BN;

    const float* Ag = g_Xc   + (size_t)bm * K;
    const float* Bg = g_Weff + (size_t)bn * K;

    float c[4][8][4];
    #pragma unroll
    for (int mt = 0; mt < 4; mt++)
        #pragma unroll
        for (int nt = 0; nt < 8; nt++)
            #pragma unroll
            for (int r = 0; r < 4; r++)
                c[mt][nt][r] = 0.0f;

    const int KT = K / BK;   // 32

    // prologue: stages 0,1
    issue_tile(Ag, Bg, K, KT, a_base, b_base, tid, 0, 0);
    issue_tile(Ag, Bg, K, KT, a_base, b_base, tid, 1, 1);

    const int t  = lane & 3;           // threadID within mma group
    const int gr = lane >> 2;          // mma groupID (row/col within tile)

    for (int kt = 0; kt < KT; kt++) {
        const int s = kt % NS;
        asm volatile("cp.async.wait_group %0;" :: "n"(NS - 2) : "memory");
        __syncthreads();
        // refill slot (kt+2)%NS == slot of compute(kt-1), safe after the sync
        issue_tile(Ag, Bg, K, KT, a_base, b_base, tid, kt + 2, (kt + 2) % NS);

        const float* As = smem + s * STAGE_ELE;
        const float* Bs = As + A_ELE;

        #pragma unroll
        for (int g = 0; g < 4; g++) {              // 4 x (k=8) steps
            const int kp = g * 8 + 2 * t;          // interleaved: (k, k+4) pair
            uint32_t afr[4][4];
            uint32_t bfr[8][2];
            const int ar = wm * 64 + gr;
            #pragma unroll
            for (int mt = 0; mt < 4; mt++) {
                uint2 v0 = *reinterpret_cast<const uint2*>(As + (ar + mt * 16) * SST + kp);
                uint2 v1 = *reinterpret_cast<const uint2*>(As + (ar + mt * 16 + 8) * SST + kp);
                afr[mt][0] = v0.x;   // (row,   k)
                afr[mt][1] = v1.x;   // (row+8, k)
                afr[mt][2] = v0.y;   // (row,   k+4)
                afr[mt][3] = v1.y;   // (row+8, k+4)
            }
            const int br = wn * 64 + gr;
            #pragma unroll
            for (int nt = 0; nt < 8; nt++) {
                uint2 w = *reinterpret_cast<const uint2*>(Bs + (br + nt * 8) * SST + kp);
                bfr[nt][0] = w.x;    // (col, k)
                bfr[nt][1] = w.y;    // (col, k+4)
            }
            #pragma unroll
            for (int mt = 0; mt < 4; mt++)
                #pragma unroll
                for (int nt = 0; nt < 8; nt++)
                    mma8(c[mt][nt], afr[mt], bfr[nt]);
        }
    }

    // epilogue: += bias, store float2
    #pragma unroll
    for (int mt = 0; mt < 4; mt++) {
        int row0 = bm + wm * 64 + mt * 16 + gr;
        #pragma unroll
        for (int nt = 0; nt < 8; nt++) {
            int col = bn + wn * 64 + nt * 8 + t * 2;
            float2 bv = *reinterpret_cast<const float2*>(bias + col);
            float2 v0 = { c[mt][nt][0] + bv.x, c[mt][nt][1] + bv.y };
            float2 v1 = { c[mt][nt][2] + bv.x, c[mt][nt][3] + bv.y };
            *reinterpret_cast<float2*>(C + (size_t)row0 * N + col)       = v0;
            *reinterpret_cast<float2*>(C + (size_t)(row0 + 8) * N + col) = v1;
        }
    }
}

// ---- launch ----------------------------------------------------------------
extern "C" void kernel_launch(void* const* d_in, const int* in_sizes, int n_in,
                              void* d_out, int out_size) {
    (void)n_in; (void)out_size;
    const float* x  = (const float*)d_in[0];
    const float* W  = (const float*)d_in[1];
    const float* b  = (const float*)d_in[2];
    const float* gA = (const float*)d_in[3];
    const float* gB = (const float*)d_in[4];
    const float* lA = (const float*)d_in[5];
    const float* lB = (const float*)d_in[6];

    const int N = in_sizes[2];               // 4096
    const int K = in_sizes[1] / N;           // 1024
    const int R = in_sizes[4] / N;           // 8
    const int M = in_sizes[0] / K;           // 16384

    // k1: x -> tf32, k-pair interleaved
    int n8 = (M * K) / 8;
    cvt_x_kernel<<<(n8 + 255) / 256, 256>>>((const float4*)x, n8);

    // k2: Weff, k-pair interleaved
    int K8 = K / 8;
    int t8 = N * K8;
    weff_kernel<<<(t8 + 255) / 256, 256>>>((const float4*)W, (const float4*)gA, gB,
                                           (const float4*)lA, lB, K8, R, t8);

    // k3: GEMM
    cudaFuncSetAttribute(gemm_tf32_kernel,
                         cudaFuncAttributeMaxDynamicSharedMemorySize, GEMM_SMEM_BYTES);
    dim3 grid(N / BN, M / BM);   // (16, 128)
    gemm_tf32_kernel<<<grid, 256, GEMM_SMEM_BYTES>>>(b, (float*)d_out, M, N, K);
}

// round 13
// speedup vs baseline: 1.8593x; 1.7367x over previous
#include <cuda_runtime.h>
#include <cuda_fp16.h>
#include <cstdint>
#include <cstddef>

// ----------------------------------------------------------------------------
// LoRALinear: out = x @ Weff^T + b, Weff = W + 2*(gB@gA + lB@lA)
//   k1: fp16-round x -> g_Xh   (k-permuted per 16: [k0,k1,k8,k9, k2,k3,k10,k11,
//                                                   k4,k5,k12,k13, k6,k7,k14,k15])
//   k2: fold LoRA -> g_Wh      (same permute)
//   k3: mma.sync m16n8k16 f16 GEMM (fp32 accum), BM=128 BN=256 BK=64,
//       3-stage cp.async ring, LDS.64 fragment loads.
// fp16 mantissa == tf32 mantissa (10 bits) -> same rel_err, 2x mma rate.
// ----------------------------------------------------------------------------

#define LORA_SCALE 2.0f
#define MAXM 16384
#define MAXK 1024
#define MAXN 4096

__device__ __half g_Xh[MAXM * MAXK];    // 32 MB scratch (permuted-k fp16)
__device__ __half g_Wh[MAXN * MAXK];    // 8 MB scratch (permuted-k fp16)

// ---- kernel 1: x -> fp16, 16-k permute -------------------------------------
__global__ void cvt_x_kernel(const float4* __restrict__ x, int n16) {
    int i = blockIdx.x * blockDim.x + threadIdx.x;
    if (i >= n16) return;
    float4 a = x[4 * i + 0];   // k0..3
    float4 b = x[4 * i + 1];   // k4..7
    float4 c = x[4 * i + 2];   // k8..11
    float4 d = x[4 * i + 3];   // k12..15
    __half2 h[8];
    h[0] = __floats2half2_rn(a.x, a.y);   // k0,k1
    h[1] = __floats2half2_rn(c.x, c.y);   // k8,k9
    h[2] = __floats2half2_rn(a.z, a.w);   // k2,k3
    h[3] = __floats2half2_rn(c.z, c.w);   // k10,k11
    h[4] = __floats2half2_rn(b.x, b.y);   // k4,k5
    h[5] = __floats2half2_rn(d.x, d.y);   // k12,k13
    h[6] = __floats2half2_rn(b.z, b.w);   // k6,k7
    h[7] = __floats2half2_rn(d.z, d.w);   // k14,k15
    uint4* out = reinterpret_cast<uint4*>(g_Xh);
    const uint32_t* u = reinterpret_cast<const uint32_t*>(h);
    out[2 * i]     = make_uint4(u[0], u[1], u[2], u[3]);
    out[2 * i + 1] = make_uint4(u[4], u[5], u[6], u[7]);
}

// ---- kernel 2: Weff = fp16( W + SCALE*(gB@gA + lB@lA) ), permuted ----------
__global__ void weff_kernel(const float4* __restrict__ W,
                            const float4* __restrict__ gA,
                            const float*  __restrict__ gB,
                            const float4* __restrict__ lA,
                            const float*  __restrict__ lB,
                            int K16, int R, int total16) {
    int i = blockIdx.x * blockDim.x + threadIdx.x;
    if (i >= total16) return;
    int o = i / K16;
    int g = i - o * K16;                 // 16-k group in row
    int K4 = K16 * 4;
    float4 acc[4];
    #pragma unroll
    for (int j = 0; j < 4; j++) acc[j] = W[4 * i + j];
    for (int r = 0; r < R; r++) {
        float gb = gB[o * R + r] * LORA_SCALE;
        float lb = lB[o * R + r] * LORA_SCALE;
        #pragma unroll
        for (int j = 0; j < 4; j++) {
            float4 ga = gA[r * K4 + 4 * g + j];
            float4 la = lA[r * K4 + 4 * g + j];
            acc[j].x += gb * ga.x + lb * la.x;
            acc[j].y += gb * ga.y + lb * la.y;
            acc[j].z += gb * ga.z + lb * la.z;
            acc[j].w += gb * ga.w + lb * la.w;
        }
    }
    __half2 h[8];
    h[0] = __floats2half2_rn(acc[0].x, acc[0].y);
    h[1] = __floats2half2_rn(acc[2].x, acc[2].y);
    h[2] = __floats2half2_rn(acc[0].z, acc[0].w);
    h[3] = __floats2half2_rn(acc[2].z, acc[2].w);
    h[4] = __floats2half2_rn(acc[1].x, acc[1].y);
    h[5] = __floats2half2_rn(acc[3].x, acc[3].y);
    h[6] = __floats2half2_rn(acc[1].z, acc[1].w);
    h[7] = __floats2half2_rn(acc[3].z, acc[3].w);
    uint4* out = reinterpret_cast<uint4*>(g_Wh);
    const uint32_t* u = reinterpret_cast<const uint32_t*>(h);
    out[2 * i]     = make_uint4(u[0], u[1], u[2], u[3]);
    out[2 * i + 1] = make_uint4(u[4], u[5], u[6], u[7]);
}

// ---- kernel 3: GEMM --------------------------------------------------------
#define BM 128
#define BN 256
#define BK 64
#define NS 3
#define SSTH 80                          // halves per row slot (160 B stride)
#define A_H (BM * SSTH)                  // 10240 halves / stage
#define B_H (BN * SSTH)                  // 20480 halves / stage
#define STAGE_H (A_H + B_H)              // 30720 halves
#define GEMM_SMEM_BYTES (NS * STAGE_H * 2)   // 184320 B

__device__ __forceinline__ void cp16(uint32_t dst, const void* src) {
    asm volatile("cp.async.cg.shared.global [%0], [%1], 16;" :: "r"(dst), "l"(src));
}

__device__ __forceinline__ void mma16(float* c, const uint32_t* a, const uint32_t* b) {
    asm volatile(
        "mma.sync.aligned.m16n8k16.row.col.f32.f16.f16.f32 "
        "{%0,%1,%2,%3}, {%4,%5,%6,%7}, {%8,%9}, {%0,%1,%2,%3};"
        : "+f"(c[0]), "+f"(c[1]), "+f"(c[2]), "+f"(c[3])
        : "r"(a[0]), "r"(a[1]), "r"(a[2]), "r"(a[3]), "r"(b[0]), "r"(b[1]));
}

// issue cp.async group for K-tile kt into slot s (always commits a group)
// Each quarter-warp fills one contiguous 128B row-chunk -> conflict-free.
__device__ __forceinline__ void issue_tile(const __half* Ag, const __half* Bg,
                                           int K, int KT, uint32_t a_base,
                                           int tid, int kt, int s) {
    if (kt < KT) {
        const int r0  = tid >> 3;            // 0..31
        const int ch  = tid & 7;             // 16B chunk within 128B row
        const int kof = kt * BK + ch * 8;    // halves
        const uint32_t sb = a_base + (uint32_t)(s * STAGE_H) * 2u;
        #pragma unroll
        for (int i = 0; i < 4; i++) {        // A: 128 rows x 160B
            int row = r0 + 32 * i;
            cp16(sb + (uint32_t)row * 160u + (uint32_t)ch * 16u,
                 Ag + (size_t)row * K + kof);
        }
        const uint32_t bb = sb + (uint32_t)A_H * 2u;
        #pragma unroll
        for (int i = 0; i < 8; i++) {        // B: 256 rows x 160B
            int row = r0 + 32 * i;
            cp16(bb + (uint32_t)row * 160u + (uint32_t)ch * 16u,
                 Bg + (size_t)row * K + kof);
        }
    }
    asm volatile("cp.async.commit_group;" ::: "memory");
}

__global__ void __launch_bounds__(256, 1)
gemm_f16_kernel(const float* __restrict__ bias, float* __restrict__ C,
                int M, int N, int K) {
    extern __shared__ __half smem[];
    uint32_t a_base = (uint32_t)__cvta_generic_to_shared(smem);

    const int tid  = threadIdx.x;
    const int lane = tid & 31;
    const int warp = tid >> 5;
    const int wm   = warp & 1;        // 2 warps over M (64 each)
    const int wn   = warp >> 1;       // 4 warps over N (64 each)
    const int bm   = blockIdx.y * BM;
    const int bn   = blockIdx.x * BN;

    const __half* Ag = g_Xh + (size_t)bm * K;
    const __half* Bg = g_Wh + (size_t)bn * K;

    float c[4][8][4];
    #pragma unroll
    for (int mt = 0; mt < 4; mt++)
        #pragma unroll
        for (int nt = 0; nt < 8; nt++)
            #pragma unroll
            for (int r = 0; r < 4; r++)
                c[mt][nt][r] = 0.0f;

    const int KT = K / BK;            // 16

    issue_tile(Ag, Bg, K, KT, a_base, tid, 0, 0);
    issue_tile(Ag, Bg, K, KT, a_base, tid, 1, 1);

    const int t  = lane & 3;          // threadID in mma group
    const int gr = lane >> 2;         // groupID

    for (int kt = 0; kt < KT; kt++) {
        const int s = kt % NS;
        asm volatile("cp.async.wait_group %0;" :: "n"(NS - 2) : "memory");
        __syncthreads();
        issue_tile(Ag, Bg, K, KT, a_base, tid, kt + 2, (kt + 2) % NS);

        const __half* As = smem + s * STAGE_H;
        const __half* Bs = As + A_H;

        #pragma unroll
        for (int g = 0; g < 4; g++) {             // 4 x (k=16) steps
            const int kp = g * 16 + t * 4;        // halves: 16B kstep, 8B/lane
            uint32_t afr[4][4];
            uint32_t bfr[8][2];
            const int ar = wm * 64 + gr;
            #pragma unroll
            for (int mt = 0; mt < 4; mt++) {
                uint2 v0 = *reinterpret_cast<const uint2*>(As + (ar + mt * 16) * SSTH + kp);
                uint2 v1 = *reinterpret_cast<const uint2*>(As + (ar + mt * 16 + 8) * SSTH + kp);
                afr[mt][0] = v0.x;   // (row,   k2t..2t+1)
                afr[mt][1] = v1.x;   // (row+8, k2t..2t+1)
                afr[mt][2] = v0.y;   // (row,   k2t+8..9)
                afr[mt][3] = v1.y;   // (row+8, k2t+8..9)
            }
            const int br = wn * 64 + gr;
            #pragma unroll
            for (int nt = 0; nt < 8; nt++) {
                uint2 w = *reinterpret_cast<const uint2*>(Bs + (br + nt * 8) * SSTH + kp);
                bfr[nt][0] = w.x;
                bfr[nt][1] = w.y;
            }
            #pragma unroll
            for (int mt = 0; mt < 4; mt++)
                #pragma unroll
                for (int nt = 0; nt < 8; nt++)
                    mma16(c[mt][nt], afr[mt], bfr[nt]);
        }
    }

    // epilogue: += bias, store float2
    #pragma unroll
    for (int mt = 0; mt < 4; mt++) {
        int row0 = bm + wm * 64 + mt * 16 + gr;
        #pragma unroll
        for (int nt = 0; nt < 8; nt++) {
            int col = bn + wn * 64 + nt * 8 + t * 2;
            float2 bv = *reinterpret_cast<const float2*>(bias + col);
            float2 v0 = { c[mt][nt][0] + bv.x, c[mt][nt][1] + bv.y };
            float2 v1 = { c[mt][nt][2] + bv.x, c[mt][nt][3] + bv.y };
            *reinterpret_cast<float2*>(C + (size_t)row0 * N + col)       = v0;
            *reinterpret_cast<float2*>(C + (size_t)(row0 + 8) * N + col) = v1;
        }
    }
}

// ---- launch ----------------------------------------------------------------
extern "C" void kernel_launch(void* const* d_in, const int* in_sizes, int n_in,
                              void* d_out, int out_size) {
    (void)n_in; (void)out_size;
    const float* x  = (const float*)d_in[0];
    const float* W  = (const float*)d_in[1];
    const float* b  = (const float*)d_in[2];
    const float* gA = (const float*)d_in[3];
    const float* gB = (const float*)d_in[4];
    const float* lA = (const float*)d_in[5];
    const float* lB = (const float*)d_in[6];

    const int N = in_sizes[2];               // 4096
    const int K = in_sizes[1] / N;           // 1024
    const int R = in_sizes[4] / N;           // 8
    const int M = in_sizes[0] / K;           // 16384

    int n16 = (M * K) / 16;
    cvt_x_kernel<<<(n16 + 255) / 256, 256>>>((const float4*)x, n16);

    int K16 = K / 16;
    int t16 = N * K16;
    weff_kernel<<<(t16 + 255) / 256, 256>>>((const float4*)W, (const float4*)gA, gB,
                                            (const float4*)lA, lB, K16, R, t16);

    cudaFuncSetAttribute(gemm_f16_kernel,
                         cudaFuncAttributeMaxDynamicSharedMemorySize, GEMM_SMEM_BYTES);
    dim3 grid(N / BN, M / BM);               // (16, 128)
    gemm_f16_kernel<<<grid, 256, GEMM_SMEM_BYTES>>>(b, (float*)d_out, M, N, K);
}